// round 3
// baseline (speedup 1.0000x reference)
#include <cuda_runtime.h>
#include <math.h>

// Problem constants (KWinners2d: B=64, C=128, H=W=56)
#define NB      64
#define NC      128
#define HW      3136
#define NPB     401408          // per-batch n = C*H*W
#define NPB4    (NPB/4)         // 100352 float4 per batch
#define HW4     (HW/4)          // 784
#define NBINS   8192            // 13-bit coarse histogram
#define CAP     (1<<17)         // candidate buffer per batch
#define CPB_A   8               // CTAs per batch, histogram pass
#define CPB_C   16              // CTAs per batch, write pass
#define STAGE   2048            // per-CTA candidate staging entries

// -------- global scratch (static __device__, no allocation) --------
__device__ unsigned int       g_hist[NB * NBINS];
__device__ unsigned int       g_cand_cnt[NB];
__device__ unsigned int       g_bstar[NB];
__device__ unsigned int       g_above[NB];
__device__ unsigned long long g_cand[(size_t)NB * CAP];  // (key<<32)|idx

// order-preserving key for f32, branchless: larger float -> larger uint
__device__ __forceinline__ unsigned okey(float f) {
    unsigned u = __float_as_uint(f);
    unsigned m = (unsigned)((int)u >> 31);      // all-ones if negative
    return u ^ (m | 0x80000000u);
}

__device__ __forceinline__ float boost_factor(int k, float duty) {
    // reference: f32(k/n) - duty (f32 sub), then f32 exp.
    // double-precision exp of the f32 argument, rounded to f32 (correctly rounded).
    float td = (float)((double)k / (double)NPB);
    float arg = td - duty;
    return (float)exp((double)arg);
}

// warp-aggregated shared histogram add (all 32 lanes must be active)
__device__ __forceinline__ void hadd(unsigned* s_hist, unsigned bin, int lane) {
    unsigned mm = __match_any_sync(0xffffffffu, bin);
    int leader = __ffs(mm) - 1;
    if (lane == leader) atomicAdd(&s_hist[bin], (unsigned)__popc(mm));
}

// -------- kernel 0: zero scratch (re-zeroed every graph replay) --------
__global__ void zero_kernel() {
    int total = NB * NBINS;
    for (int i = blockIdx.x * blockDim.x + threadIdx.x; i < total;
         i += gridDim.x * blockDim.x)
        g_hist[i] = 0;
    if (blockIdx.x == 0 && threadIdx.x < NB) g_cand_cnt[threadIdx.x] = 0;
}

// -------- kernel 1: per-batch coarse histogram (13 key bits) --------
__global__ void __launch_bounds__(256) hist_kernel(
        const float* __restrict__ x,
        const float* __restrict__ duty,
        const int* __restrict__ kp) {
    __shared__ unsigned s_hist[NBINS];
    __shared__ float    s_fac[NC];
    int tid = threadIdx.x;
    int lane = tid & 31;
    for (int i = tid; i < NBINS; i += 256) s_hist[i] = 0;
    if (tid < NC) s_fac[tid] = boost_factor(*kp, duty[tid]);
    __syncthreads();

    int batch = blockIdx.x / CPB_A;
    int slice = blockIdx.x % CPB_A;
    const float4* x4 = (const float4*)x + (size_t)batch * NPB4;
    const int PER = NPB4 / CPB_A;              // 12544 = 49*256 (always full warps)
    int base = slice * PER;
    for (int i = tid; i < PER; i += 256) {
        int q = base + i;
        float f = s_fac[q / HW4];
        float4 v = x4[q];
        hadd(s_hist, okey(v.x * f) >> 19, lane);
        hadd(s_hist, okey(v.y * f) >> 19, lane);
        hadd(s_hist, okey(v.z * f) >> 19, lane);
        hadd(s_hist, okey(v.w * f) >> 19, lane);
    }
    __syncthreads();
    unsigned* gh = &g_hist[batch * NBINS];
    for (int i = tid; i < NBINS; i += 256)
        if (s_hist[i]) atomicAdd(&gh[i], s_hist[i]);
}

// -------- kernel 2: per batch, find bin containing the k-th largest --------
__global__ void __launch_bounds__(1024) findbin_kernel(const int* __restrict__ kp) {
    __shared__ unsigned s_sum[1024];
    int batch = blockIdx.x, tid = threadIdx.x;
    const unsigned* gh = &g_hist[batch * NBINS];
    // thread t sums a descending chunk of 8 bins
    unsigned s = 0;
    int hi = NBINS - 1 - tid * 8;
    for (int j = 0; j < 8; j++) s += gh[hi - j];
    s_sum[tid] = s;
    __syncthreads();
    if (tid == 0) {
        unsigned k = (unsigned)(*kp);
        unsigned cum = 0;
        for (int j = 0; j < 1024; j++) {
            if (cum + s_sum[j] >= k) {
                for (int b = NBINS - 1 - j * 8;; b--) {
                    unsigned h = gh[b];
                    if (cum + h >= k) { g_bstar[batch] = (unsigned)b; g_above[batch] = cum; break; }
                    cum += h;
                }
                break;
            }
            cum += s_sum[j];
        }
    }
}

// -------- kernel 3: write clear winners/losers, stage boundary bin in smem --------
__global__ void __launch_bounds__(256) write_kernel(
        const float* __restrict__ x,
        const float* __restrict__ duty,
        const int* __restrict__ kp,
        float* __restrict__ out) {
    __shared__ float             s_fac[NC];
    __shared__ unsigned long long s_buf[STAGE];
    __shared__ unsigned          s_cnt;
    int tid = threadIdx.x;
    if (tid < NC) s_fac[tid] = boost_factor(*kp, duty[tid]);
    if (tid == 0) s_cnt = 0;
    __syncthreads();

    int batch = blockIdx.x / CPB_C;
    int slice = blockIdx.x % CPB_C;
    unsigned bstar = g_bstar[batch];
    const float4* x4 = (const float4*)x + (size_t)batch * NPB4;
    float4*       o4 = (float4*)out     + (size_t)batch * NPB4;
    const int PER = NPB4 / CPB_C;              // 6272

    #pragma unroll 2
    for (int i = tid; i < PER; i += 256) {
        int q = slice * PER + i;
        float f = s_fac[q / HW4];
        float4 v = x4[q];
        unsigned k0 = okey(v.x * f), k1 = okey(v.y * f);
        unsigned k2 = okey(v.z * f), k3 = okey(v.w * f);
        unsigned b0 = k0 >> 19, b1 = k1 >> 19, b2 = k2 >> 19, b3 = k3 >> 19;
        float4 o;
        o.x = (b0 > bstar) ? v.x : 0.0f;
        o.y = (b1 > bstar) ? v.y : 0.0f;
        o.z = (b2 > bstar) ? v.z : 0.0f;
        o.w = (b3 > bstar) ? v.w : 0.0f;
        __stcs(&o4[q], o);                     // streaming store: keep x resident in L2
        unsigned e = (unsigned)q * 4u;
        // rare path: ~1% of elements land in the boundary bin
        if (b0 == bstar) {
            unsigned p = atomicAdd(&s_cnt, 1u);
            unsigned long long cv = ((unsigned long long)k0 << 32) | (e + 0u);
            if (p < STAGE) s_buf[p] = cv;
            else { unsigned g = atomicAdd(&g_cand_cnt[batch], 1u);
                   if (g < CAP) g_cand[(size_t)batch * CAP + g] = cv; }
        }
        if (b1 == bstar) {
            unsigned p = atomicAdd(&s_cnt, 1u);
            unsigned long long cv = ((unsigned long long)k1 << 32) | (e + 1u);
            if (p < STAGE) s_buf[p] = cv;
            else { unsigned g = atomicAdd(&g_cand_cnt[batch], 1u);
                   if (g < CAP) g_cand[(size_t)batch * CAP + g] = cv; }
        }
        if (b2 == bstar) {
            unsigned p = atomicAdd(&s_cnt, 1u);
            unsigned long long cv = ((unsigned long long)k2 << 32) | (e + 2u);
            if (p < STAGE) s_buf[p] = cv;
            else { unsigned g = atomicAdd(&g_cand_cnt[batch], 1u);
                   if (g < CAP) g_cand[(size_t)batch * CAP + g] = cv; }
        }
        if (b3 == bstar) {
            unsigned p = atomicAdd(&s_cnt, 1u);
            unsigned long long cv = ((unsigned long long)k3 << 32) | (e + 3u);
            if (p < STAGE) s_buf[p] = cv;
            else { unsigned g = atomicAdd(&g_cand_cnt[batch], 1u);
                   if (g < CAP) g_cand[(size_t)batch * CAP + g] = cv; }
        }
    }
    __syncthreads();

    // flush staged candidates: one global atomic per CTA, coalesced copy
    __shared__ unsigned s_base;
    unsigned cnt = min(s_cnt, (unsigned)STAGE);
    if (tid == 0) s_base = atomicAdd(&g_cand_cnt[batch], cnt);
    __syncthreads();
    unsigned base = s_base;
    for (unsigned j = tid; j < cnt; j += 256) {
        unsigned pos = base + j;
        if (pos < CAP) g_cand[(size_t)batch * CAP + pos] = s_buf[j];
    }
}

// -------- kernel 4: exact selection among boundary-bin candidates --------
__global__ void final_kernel(const float* __restrict__ x,
                             const int* __restrict__ kp,
                             float* __restrict__ out) {
    __shared__ unsigned s_h[2048];
    __shared__ unsigned s_chunk[64];
    __shared__ unsigned s_eq[2048];
    __shared__ unsigned s_eqcnt, s_b1, s_g1, s_tl, s_r2;
    int batch = blockIdx.x, tid = threadIdx.x, nt = blockDim.x;
    unsigned m = min(g_cand_cnt[batch], (unsigned)CAP);
    unsigned k = (unsigned)(*kp);
    unsigned r = k - g_above[batch];           // winners still needed, 1..m
    const unsigned long long* cand = &g_cand[(size_t)batch * CAP];
    const float* xb = x   + (size_t)batch * NPB;
    float*       ob = out + (size_t)batch * NPB;

    if (r >= m) {                               // everything in the bin wins
        for (unsigned j = tid; j < m; j += nt) {
            unsigned idx = (unsigned)cand[j];
            ob[idx] = xb[idx];
        }
        return;
    }

    // level 1: histogram on key bits [18:8]
    for (int i = tid; i < 2048; i += nt) s_h[i] = 0;
    __syncthreads();
    for (unsigned j = tid; j < m; j += nt) {
        unsigned key = (unsigned)(cand[j] >> 32);
        atomicAdd(&s_h[(key >> 8) & 0x7FFu], 1u);
    }
    __syncthreads();
    if (tid < 64) {
        unsigned s = 0; int hi = 2047 - tid * 32;
        for (int j = 0; j < 32; j++) s += s_h[hi - j];
        s_chunk[tid] = s;
    }
    __syncthreads();
    if (tid == 0) {
        unsigned cum = 0;
        for (int j = 0; j < 64; j++) {
            if (cum + s_chunk[j] >= r) {
                for (int b = 2047 - 32 * j;; b--) {
                    unsigned h = s_h[b];
                    if (cum + h >= r) { s_b1 = (unsigned)b; s_g1 = cum; break; }
                    cum += h;
                }
                break;
            }
            cum += s_chunk[j];
        }
    }
    __syncthreads();
    unsigned b1 = s_b1, g1 = s_g1;

    // level 2: histogram on key bits [7:0] among b1 matches
    for (int i = tid; i < 256; i += nt) s_h[i] = 0;
    __syncthreads();
    for (unsigned j = tid; j < m; j += nt) {
        unsigned key = (unsigned)(cand[j] >> 32);
        if (((key >> 8) & 0x7FFu) == b1) atomicAdd(&s_h[key & 0xFFu], 1u);
    }
    __syncthreads();
    if (tid == 0) {
        unsigned cum = g1;
        for (int b = 255;; b--) {
            unsigned h = s_h[b];
            if (cum + h >= r) { s_tl = (b1 << 8) | (unsigned)b; s_r2 = r - cum; break; }
            cum += h;
        }
        s_eqcnt = 0;
    }
    __syncthreads();
    unsigned tl = s_tl, r2 = s_r2;

    // write strict winners; collect exact-threshold ties
    for (unsigned j = tid; j < m; j += nt) {
        unsigned long long cv = cand[j];
        unsigned key = (unsigned)(cv >> 32);
        unsigned l = key & 0x7FFFFu;
        unsigned idx = (unsigned)cv;
        if (l > tl) ob[idx] = xb[idx];
        else if (l == tl) {
            unsigned p = atomicAdd(&s_eqcnt, 1u);
            if (p < 2048u) s_eq[p] = idx;
        }
    }
    __syncthreads();
    unsigned e = min(s_eqcnt, 2048u);
    if (r2 >= e) {
        for (unsigned j = tid; j < e; j += nt) { unsigned idx = s_eq[j]; ob[idx] = xb[idx]; }
    } else {
        // ties broken by LOWEST index (matches jax.lax.top_k)
        for (unsigned j = tid; j < e; j += nt) {
            unsigned idx = s_eq[j], rank = 0;
            for (unsigned l2 = 0; l2 < e; l2++) rank += (s_eq[l2] < idx) ? 1u : 0u;
            if (rank < r2) ob[idx] = xb[idx];
        }
    }
}

extern "C" void kernel_launch(void* const* d_in, const int* in_sizes, int n_in,
                              void* d_out, int out_size) {
    const float* x    = (const float*)d_in[0];
    const float* duty = (const float*)d_in[1];
    const int*   kp   = (const int*)d_in[2];
    float*       out  = (float*)d_out;

    zero_kernel<<<256, 256>>>();
    hist_kernel<<<NB * CPB_A, 256>>>(x, duty, kp);
    findbin_kernel<<<NB, 1024>>>(kp);
    write_kernel<<<NB * CPB_C, 256>>>(x, duty, kp, out);
    final_kernel<<<NB, 256>>>(x, kp, out);
}

// round 4
// speedup vs baseline: 1.8332x; 1.8332x over previous
#include <cuda_runtime.h>
#include <math.h>

// Problem constants (KWinners2d: B=64, C=128, H=W=56)
#define NB      64
#define NC      128
#define HW      3136
#define NPB     401408          // per-batch n = C*H*W
#define NPB4    (NPB/4)         // 100352 float4 per batch
#define HW4     (HW/4)          // 784
#define NBINS   8192            // 13-bit coarse histogram
#define CAP     (1<<17)         // candidate buffer per batch
#define CPB_S   2               // CTAs per batch, sample pass
#define CPB_C   32              // CTAs per batch, write pass
#define STAGE   2048            // per-CTA candidate staging entries
#define MS      50176           // samples (values) per batch = NPB/8
#define MARGIN  502             // ~1% of NPB in sample-rank units (MS*0.01)

// -------- global scratch (static __device__, no allocation) --------
__device__ unsigned int       g_hist[NB * NBINS];
__device__ unsigned int       g_cand_cnt[NB];
__device__ unsigned int       g_bhi[NB];
__device__ unsigned int       g_blo[NB];
__device__ unsigned int       g_above[NB];
__device__ unsigned long long g_cand[(size_t)NB * CAP];  // (key<<32)|idx

// order-preserving key for f32: larger float -> larger uint
__device__ __forceinline__ unsigned okey(float f) {
    unsigned u = __float_as_uint(f);
    unsigned mневid = (unsigned)((int)u >> 31);
    return u ^ (mневid | 0x80000000u);
}

__device__ __forceinline__ float boost_factor(int k, float duty) {
    // reference: f32(k/n) - duty (f32 sub), then f32 exp.
    // double exp of the f32 argument, rounded to f32 (correctly rounded).
    float td = (float)((double)k / (double)NPB);
    float arg = td - duty;
    return (float)exp((double)arg);
}

// -------- kernel 0: zero scratch (re-zeroed every graph replay) --------
__global__ void zero_kernel() {
    int total = NB * NBINS;
    for (int i = blockIdx.x * blockDim.x + threadIdx.x; i < total;
         i += gridDim.x * blockDim.x)
        g_hist[i] = 0;
    if (blockIdx.x == 0 && threadIdx.x < NB) {
        g_cand_cnt[threadIdx.x] = 0;
        g_above[threadIdx.x] = 0;
    }
}

// -------- kernel 1: SAMPLED per-batch coarse histogram (1/8 of data) --------
__global__ void __launch_bounds__(256) sample_kernel(
        const float* __restrict__ x,
        const float* __restrict__ duty,
        const int* __restrict__ kp) {
    __shared__ unsigned s_hist[NBINS];
    __shared__ float    s_fac[NC];
    int tid = threadIdx.x;
    for (int i = tid; i < NBINS; i += 256) s_hist[i] = 0;
    if (tid < NC) s_fac[tid] = boost_factor(*kp, duty[tid]);
    __syncthreads();

    int batch = blockIdx.x / CPB_S;
    int slice = blockIdx.x % CPB_S;
    const float4* x4 = (const float4*)x + (size_t)batch * NPB4;
    int base = slice * (NPB4 / CPB_S);         // 50176
    // 6272 sampled float4 per CTA: warp reads 32 contiguous float4, skips 8x
    for (int j = tid; j < 6272; j += 256) {
        int q = base + ((j >> 5) << 8) + (j & 31);
        float f = s_fac[q / HW4];
        float4 v = x4[q];
        unsigned b0 = okey(v.x * f) >> 19;
        unsigned b1 = okey(v.y * f) >> 19;
        unsigned b2 = okey(v.z * f) >> 19;
        unsigned b3 = okey(v.w * f) >> 19;
        unsigned c0 = 1, c1 = 1, c2 = 1, c3 = 1;
        if (b1 == b0) { c0++; c1 = 0; }
        if (b2 == b0) { c0++; c2 = 0; }
        else if (c1 && b2 == b1) { c1++; c2 = 0; }
        if (b3 == b0) { c0++; c3 = 0; }
        else if (c1 && b3 == b1) { c1++; c3 = 0; }
        else if (c2 && b3 == b2) { c2++; c3 = 0; }
        atomicAdd(&s_hist[b0], c0);
        if (c1) atomicAdd(&s_hist[b1], c1);
        if (c2) atomicAdd(&s_hist[b2], c2);
        if (c3) atomicAdd(&s_hist[b3], c3);
    }
    __syncthreads();
    unsigned* gh = &g_hist[batch * NBINS];
    for (int i = tid; i < NBINS; i += 256)
        if (s_hist[i]) atomicAdd(&gh[i], s_hist[i]);
}

// -------- kernel 2: pick window [b_lo, b_hi] from sampled ranks --------
__global__ void __launch_bounds__(1024) window_kernel(const int* __restrict__ kp) {
    __shared__ unsigned s_sum[1024];
    int batch = blockIdx.x, tid = threadIdx.x;
    const unsigned* gh = &g_hist[batch * NBINS];
    unsigned s = 0;
    int hi = NBINS - 1 - tid * 8;
    for (int j = 0; j < 8; j++) s += gh[hi - j];
    s_sum[tid] = s;
    __syncthreads();
    if (tid == 0) {
        unsigned k = (unsigned)(*kp);
        unsigned ks = (unsigned)((unsigned long long)k * MS / NPB);
        unsigned khi = (ks > MARGIN) ? ks - MARGIN : 1u;
        unsigned klo = ks + MARGIN; if (klo > MS) klo = MS;
        unsigned cum = 0;
        int bhi = -1, blo = -1;
        for (int j = 0; j < 1024 && blo < 0; j++) {
            unsigned nc = cum + s_sum[j];
            if ((bhi < 0 && nc >= khi) || nc >= klo) {
                int b = NBINS - 1 - 8 * j;
                for (int t = 0; t < 8; t++, b--) {
                    unsigned h = gh[b];
                    if (bhi < 0 && cum + h >= khi) bhi = b;
                    if (blo < 0 && cum + h >= klo) { blo = b; break; }
                    cum += h;
                }
            } else cum = nc;
        }
        g_bhi[batch] = (unsigned)bhi;
        g_blo[batch] = (unsigned)blo;
    }
}

// -------- kernel 3: write output, exact above-count, stage window cands --------
__global__ void __launch_bounds__(256) write_kernel(
        const float* __restrict__ x,
        const float* __restrict__ duty,
        const int* __restrict__ kp,
        float* __restrict__ out) {
    __shared__ float              s_fac[NC];
    __shared__ unsigned long long s_buf[STAGE];
    __shared__ unsigned           s_cnt, s_w, s_base;
    int tid = threadIdx.x;
    if (tid < NC) s_fac[tid] = boost_factor(*kp, duty[tid]);
    if (tid == 0) { s_cnt = 0; s_w = 0; }
    __syncthreads();

    int batch = blockIdx.x / CPB_C;
    int slice = blockIdx.x % CPB_C;
    unsigned bhi = g_bhi[batch];
    unsigned blo = g_blo[batch];
    const float4* x4 = (const float4*)x + (size_t)batch * NPB4;
    float4*       o4 = (float4*)out     + (size_t)batch * NPB4;
    const int PER = NPB4 / CPB_C;              // 3136
    unsigned wc = 0;

    #pragma unroll 2
    for (int i = tid; i < PER; i += 256) {
        int q = slice * PER + i;
        float f = s_fac[q / HW4];
        float4 v = x4[q];
        unsigned k0 = okey(v.x * f), k1 = okey(v.y * f);
        unsigned k2 = okey(v.z * f), k3 = okey(v.w * f);
        unsigned b0 = k0 >> 19, b1 = k1 >> 19, b2 = k2 >> 19, b3 = k3 >> 19;
        float4 o;
        o.x = (b0 > bhi) ? v.x : 0.0f;
        o.y = (b1 > bhi) ? v.y : 0.0f;
        o.z = (b2 > bhi) ? v.z : 0.0f;
        o.w = (b3 > bhi) ? v.w : 0.0f;
        o4[q] = o;
        wc += (b0 > bhi) + (b1 > bhi) + (b2 > bhi) + (b3 > bhi);
        unsigned e = (unsigned)q * 4u;
        // rare path: ~3% of elements land inside the window
        if (b0 >= blo && b0 <= bhi) {
            unsigned p = atomicAdd(&s_cnt, 1u);
            unsigned long long cv = ((unsigned long long)k0 << 32) | (e + 0u);
            if (p < STAGE) s_buf[p] = cv;
            else { unsigned g = atomicAdd(&g_cand_cnt[batch], 1u);
                   if (g < CAP) g_cand[(size_t)batch * CAP + g] = cv; }
        }
        if (b1 >= blo && b1 <= bhi) {
            unsigned p = atomicAdd(&s_cnt, 1u);
            unsigned long long cv = ((unsigned long long)k1 << 32) | (e + 1u);
            if (p < STAGE) s_buf[p] = cv;
            else { unsigned g = atomicAdd(&g_cand_cnt[batch], 1u);
                   if (g < CAP) g_cand[(size_t)batch * CAP + g] = cv; }
        }
        if (b2 >= blo && b2 <= bhi) {
            unsigned p = atomicAdd(&s_cnt, 1u);
            unsigned long long cv = ((unsigned long long)k2 << 32) | (e + 2u);
            if (p < STAGE) s_buf[p] = cv;
            else { unsigned g = atomicAdd(&g_cand_cnt[batch], 1u);
                   if (g < CAP) g_cand[(size_t)batch * CAP + g] = cv; }
        }
        if (b3 >= blo && b3 <= bhi) {
            unsigned p = atomicAdd(&s_cnt, 1u);
            unsigned long long cv = ((unsigned long long)k3 << 32) | (e + 3u);
            if (p < STAGE) s_buf[p] = cv;
            else { unsigned g = atomicAdd(&g_cand_cnt[batch], 1u);
                   if (g < CAP) g_cand[(size_t)batch * CAP + g] = cv; }
        }
    }
    // exact winners-above-window count: one global atomic per CTA
    #pragma unroll
    for (int o = 16; o; o >>= 1) wc += __shfl_down_sync(0xffffffffu, wc, o);
    if ((tid & 31) == 0 && wc) atomicAdd(&s_w, wc);
    __syncthreads();
    if (tid == 0) {
        if (s_w) atomicAdd(&g_above[batch], s_w);
        s_base = atomicAdd(&g_cand_cnt[batch], min(s_cnt, (unsigned)STAGE));
    }
    __syncthreads();
    unsigned cnt = min(s_cnt, (unsigned)STAGE);
    unsigned base = s_base;
    for (unsigned j = tid; j < cnt; j += 256) {
        unsigned pos = base + j;
        if (pos < CAP) g_cand[(size_t)batch * CAP + pos] = s_buf[j];
    }
}

// -------- kernel 4: validate window; exact selection (or exact fallback) ----
__global__ void __launch_bounds__(1024) final_kernel(
        const float* __restrict__ x,
        const float* __restrict__ duty,
        const int* __restrict__ kp,
        float* __restrict__ out) {
    __shared__ unsigned s_h[NBINS];
    __shared__ unsigned s_sum[1024];
    __shared__ unsigned s_eq[2048];
    __shared__ float    s_fac[NC];
    __shared__ unsigned s_cnt, s_B1, s_g1, s_tl, s_r2, s_bstar, s_above;
    int batch = blockIdx.x, tid = threadIdx.x;
    unsigned k = (unsigned)(*kp);
    unsigned m = g_cand_cnt[batch];
    unsigned above = g_above[batch];
    unsigned blo = g_blo[batch], bhi = g_bhi[batch];
    unsigned long long* cand = &g_cand[(size_t)batch * CAP];
    const float* xb = x   + (size_t)batch * NPB;
    float*       ob = out + (size_t)batch * NPB;
    unsigned r;

    bool valid = (above < k) && (k <= above + m) && (m <= (unsigned)CAP) &&
                 (bhi - blo < 16u);
    if (valid) {
        r = k - above;
    } else {
        // ---------- exact fallback: full recompute for this batch ----------
        if (tid < NC) s_fac[tid] = boost_factor((int)k, duty[tid]);
        for (int i = tid; i < NBINS; i += 1024) s_h[i] = 0;
        __syncthreads();
        const float4* x4 = (const float4*)xb;
        for (int q = tid; q < NPB4; q += 1024) {
            float f = s_fac[q / HW4];
            float4 v = x4[q];
            atomicAdd(&s_h[okey(v.x * f) >> 19], 1u);
            atomicAdd(&s_h[okey(v.y * f) >> 19], 1u);
            atomicAdd(&s_h[okey(v.z * f) >> 19], 1u);
            atomicAdd(&s_h[okey(v.w * f) >> 19], 1u);
        }
        __syncthreads();
        {
            unsigned s = 0; int hi2 = NBINS - 1 - tid * 8;
            for (int j = 0; j < 8; j++) s += s_h[hi2 - j];
            s_sum[tid] = s;
        }
        __syncthreads();
        if (tid == 0) {
            unsigned cum = 0;
            for (int j = 0; j < 1024; j++) {
                if (cum + s_sum[j] >= k) {
                    for (int b = NBINS - 1 - 8 * j;; b--) {
                        unsigned h = s_h[b];
                        if (cum + h >= k) { s_bstar = (unsigned)b; s_above = cum; break; }
                        cum += h;
                    }
                    break;
                }
                cum += s_sum[j];
            }
            s_cnt = 0;
        }
        __syncthreads();
        unsigned bstar = s_bstar;
        r = k - s_above;
        float4* o4 = (float4*)ob;
        for (int q = tid; q < NPB4; q += 1024) {
            float f = s_fac[q / HW4];
            float4 v = x4[q];
            unsigned k0 = okey(v.x * f), k1 = okey(v.y * f);
            unsigned k2 = okey(v.z * f), k3 = okey(v.w * f);
            unsigned b0 = k0 >> 19, b1 = k1 >> 19, b2 = k2 >> 19, b3 = k3 >> 19;
            float4 o;
            o.x = (b0 > bstar) ? v.x : 0.0f;
            o.y = (b1 > bstar) ? v.y : 0.0f;
            o.z = (b2 > bstar) ? v.z : 0.0f;
            o.w = (b3 > bstar) ? v.w : 0.0f;
            o4[q] = o;
            unsigned e = (unsigned)q * 4u;
            if (b0 == bstar) { unsigned p = atomicAdd(&s_cnt, 1u);
                if (p < CAP) cand[p] = ((unsigned long long)k0 << 32) | (e + 0u); }
            if (b1 == bstar) { unsigned p = atomicAdd(&s_cnt, 1u);
                if (p < CAP) cand[p] = ((unsigned long long)k1 << 32) | (e + 1u); }
            if (b2 == bstar) { unsigned p = atomicAdd(&s_cnt, 1u);
                if (p < CAP) cand[p] = ((unsigned long long)k2 << 32) | (e + 2u); }
            if (b3 == bstar) { unsigned p = atomicAdd(&s_cnt, 1u);
                if (p < CAP) cand[p] = ((unsigned long long)k3 << 32) | (e + 3u); }
        }
        __syncthreads();
        m = min(s_cnt, (unsigned)CAP);
        blo = bstar;                 // rel-key base for the shared select below
        __syncthreads();
    }

    // quick path: everything in the window wins
    if (r >= m) {
        for (unsigned j = tid; j < m; j += 1024) {
            unsigned idx = (unsigned)cand[j];
            ob[idx] = xb[idx];
        }
        return;
    }

    unsigned base = blo << 19;       // rel-keys < 16 * 2^19 = 2^23
    // ---- level 1: histogram on rel-key bits [22:10] ----
    for (int i = tid; i < NBINS; i += 1024) s_h[i] = 0;
    __syncthreads();
    for (unsigned j = tid; j < m; j += 1024) {
        unsigned rel = (unsigned)(cand[j] >> 32) - base;
        atomicAdd(&s_h[rel >> 10], 1u);
    }
    __syncthreads();
    {
        unsigned s = 0; int hi2 = NBINS - 1 - tid * 8;
        for (int j = 0; j < 8; j++) s += s_h[hi2 - j];
        s_sum[tid] = s;
    }
    __syncthreads();
    if (tid == 0) {
        unsigned cum = 0;
        for (int j = 0; j < 1024; j++) {
            if (cum + s_sum[j] >= r) {
                for (int b = NBINS - 1 - 8 * j;; b--) {
                    unsigned h = s_h[b];
                    if (cum + h >= r) { s_B1 = (unsigned)b; s_g1 = cum; break; }
                    cum += h;
                }
                break;
            }
            cum += s_sum[j];
        }
    }
    __syncthreads();
    unsigned B1 = s_B1, g1 = s_g1;

    // ---- level 2: histogram on rel-key bits [9:0] among B1 matches ----
    for (int i = tid; i < 1024; i += 1024) s_h[i] = 0;
    __syncthreads();
    for (unsigned j = tid; j < m; j += 1024) {
        unsigned rel = (unsigned)(cand[j] >> 32) - base;
        if ((rel >> 10) == B1) atomicAdd(&s_h[rel & 1023u], 1u);
    }
    __syncthreads();
    if (tid == 0) {
        unsigned cum = g1;
        for (int b = 1023;; b--) {
            unsigned h = s_h[b];
            if (cum + h >= r) { s_tl = (B1 << 10) | (unsigned)b; s_r2 = r - cum; break; }
            cum += h;
        }
        s_cnt = 0;
    }
    __syncthreads();
    unsigned tl = s_tl, r2 = s_r2;

    // write strict winners; collect exact-threshold ties
    for (unsigned j = tid; j < m; j += 1024) {
        unsigned long long cv = cand[j];
        unsigned rel = (unsigned)(cv >> 32) - base;
        unsigned idx = (unsigned)cv;
        if (rel > tl) ob[idx] = xb[idx];
        else if (rel == tl) {
            unsigned p = atomicAdd(&s_cnt, 1u);
            if (p < 2048u) s_eq[p] = idx;
        }
    }
    __syncthreads();
    unsigned e = min(s_cnt, 2048u);
    if (r2 >= e) {
        for (unsigned j = tid; j < e; j += 1024) { unsigned idx = s_eq[j]; ob[idx] = xb[idx]; }
    } else {
        // ties broken by LOWEST index (matches jax.lax.top_k)
        for (unsigned j = tid; j < e; j += 1024) {
            unsigned idx = s_eq[j], rank = 0;
            for (unsigned l2 = 0; l2 < e; l2++) rank += (s_eq[l2] < idx) ? 1u : 0u;
            if (rank < r2) ob[idx] = xb[idx];
        }
    }
}

extern "C" void kernel_launch(void* const* d_in, const int* in_sizes, int n_in,
                              void* d_out, int out_size) {
    const float* x    = (const float*)d_in[0];
    const float* duty = (const float*)d_in[1];
    const int*   kp   = (const int*)d_in[2];
    float*       out  = (float*)d_out;

    zero_kernel<<<256, 256>>>();
    sample_kernel<<<NB * CPB_S, 256>>>(x, duty, kp);
    window_kernel<<<NB, 1024>>>(kp);
    write_kernel<<<NB * CPB_C, 256>>>(x, duty, kp, out);
    final_kernel<<<NB, 1024>>>(x, duty, kp, out);
}

// round 5
// speedup vs baseline: 2.5027x; 1.3652x over previous
#include <cuda_runtime.h>
#include <math.h>

// Problem constants (KWinners2d: B=64, C=128, H=W=56)
#define NB      64
#define NC      128
#define HW      3136
#define NPB     401408          // per-batch n = C*H*W
#define NPB4    (NPB/4)         // 100352 float4 per batch
#define HW4     784
#define NBINS   8192            // 13-bit coarse histogram
#define CAP     (1<<17)         // candidate buffer per batch
#define CPB_S   8               // CTAs per batch, sample pass
#define CPB_C   32              // CTAs per batch, write pass
#define STAGE   2048            // per-CTA candidate staging entries
#define MS      50176           // sampled values per batch = NPB/8
#define MARGIN  502             // ~6-7 sigma of sampled-rank noise

// -------- global scratch (static __device__, no allocation) --------
__device__ unsigned int       g_hist [NB * NBINS];   // sampled coarse hist
__device__ unsigned int       g_hist2[NB * NBINS];   // rel-key hist of window cands
__device__ unsigned int       g_cand_cnt[NB];
__device__ unsigned int       g_bhi[NB];
__device__ unsigned int       g_blo[NB];
__device__ unsigned int       g_above[NB];
__device__ unsigned long long g_cand[(size_t)NB * CAP];  // (key<<32)|idx

// order-preserving key for f32: larger float -> larger uint
__device__ __forceinline__ unsigned okey(float f) {
    unsigned u = __float_as_uint(f);
    unsigned s = (unsigned)((int)u >> 31);
    return u ^ (s | 0x80000000u);
}

__device__ __forceinline__ float boost_factor(int k, float duty) {
    float td = (float)((double)k / (double)NPB);
    float arg = td - duty;
    return (float)exp((double)arg);   // correctly-rounded f32 result
}

// block-wide exclusive prefix sum, blockDim.x == 1024 exactly
__device__ __forceinline__ unsigned excl_scan1024(unsigned v, unsigned* s_w, int tid) {
    __syncthreads();                              // protect s_w reuse
    int lane = tid & 31, wid = tid >> 5;
    unsigned inc = v;
    #pragma unroll
    for (int o = 1; o < 32; o <<= 1) {
        unsigned n = __shfl_up_sync(0xffffffffu, inc, o);
        if (lane >= o) inc += n;
    }
    if (lane == 31) s_w[wid] = inc;
    __syncthreads();
    if (wid == 0) {
        unsigned w = s_w[lane];
        #pragma unroll
        for (int o = 1; o < 32; o <<= 1) {
            unsigned n = __shfl_up_sync(0xffffffffu, w, o);
            if (lane >= o) w += n;
        }
        s_w[lane] = w;
    }
    __syncthreads();
    unsigned base = wid ? s_w[wid - 1] : 0u;
    return base + inc - v;
}

// -------- kernel 0: zero scratch (re-zeroed every graph replay) --------
__global__ void zero_kernel() {
    int total = NB * NBINS;
    int tid = blockIdx.x * blockDim.x + threadIdx.x;
    for (int i = tid; i < total; i += gridDim.x * blockDim.x) {
        g_hist[i] = 0; g_hist2[i] = 0;
    }
    if (blockIdx.x == 0 && threadIdx.x < NB) {
        g_cand_cnt[threadIdx.x] = 0;
        g_above[threadIdx.x] = 0;
    }
}

// -------- kernel 1: sampled coarse histogram, 8 CTAs/batch --------
__global__ void __launch_bounds__(256) sample_kernel(
        const float* __restrict__ x,
        const float* __restrict__ duty,
        const int* __restrict__ kp) {
    __shared__ unsigned s_hist[NBINS];
    __shared__ float    s_fac[NC];
    int tid = threadIdx.x;
    for (int i = tid; i < NBINS; i += 256) s_hist[i] = 0;
    if (tid < NC) s_fac[tid] = boost_factor(*kp, duty[tid]);
    __syncthreads();

    int batch = blockIdx.x / CPB_S;
    int slice = blockIdx.x % CPB_S;
    const float4* x4 = (const float4*)x + (size_t)batch * NPB4;
    int base = slice * (NPB4 / CPB_S);         // 12544 region per CTA
    // 1568 sampled float4: warp reads 32 contiguous float4 (512B), skips 8x
    for (int j = tid; j < 1568; j += 256) {
        int q = base + ((j >> 5) << 8) + (j & 31);
        float f = s_fac[q / HW4];
        float4 v = x4[q];
        unsigned b0 = okey(v.x * f) >> 19;
        unsigned b1 = okey(v.y * f) >> 19;
        unsigned b2 = okey(v.z * f) >> 19;
        unsigned b3 = okey(v.w * f) >> 19;
        unsigned c0 = 1, c1 = 1, c2 = 1, c3 = 1;
        if (b1 == b0) { c0++; c1 = 0; }
        if (b2 == b0) { c0++; c2 = 0; }
        else if (c1 && b2 == b1) { c1++; c2 = 0; }
        if (b3 == b0) { c0++; c3 = 0; }
        else if (c1 && b3 == b1) { c1++; c3 = 0; }
        else if (c2 && b3 == b2) { c2++; c3 = 0; }
        atomicAdd(&s_hist[b0], c0);
        if (c1) atomicAdd(&s_hist[b1], c1);
        if (c2) atomicAdd(&s_hist[b2], c2);
        if (c3) atomicAdd(&s_hist[b3], c3);
    }
    __syncthreads();
    unsigned* gh = &g_hist[batch * NBINS];
    for (int i = tid; i < NBINS; i += 256)
        if (s_hist[i]) atomicAdd(&gh[i], s_hist[i]);
}

// -------- kernel 2: pick window [b_lo, b_hi] via parallel suffix scan ------
__global__ void __launch_bounds__(1024) window_kernel(const int* __restrict__ kp) {
    __shared__ unsigned s_w[32];
    int batch = blockIdx.x, tid = threadIdx.x;
    const unsigned* gh = &g_hist[batch * NBINS];
    unsigned h[8], sum = 0;
    int top = NBINS - 1 - tid * 8;
    #pragma unroll
    for (int i = 0; i < 8; i++) { h[i] = gh[top - i]; sum += h[i]; }
    unsigned excl = excl_scan1024(sum, s_w, tid);   // counts in bins above chunk

    unsigned k  = (unsigned)(*kp);
    unsigned ks = (unsigned)((unsigned long long)k * MS / NPB);
    unsigned khi = (ks > MARGIN) ? ks - MARGIN : 1u;
    unsigned klo = ks + MARGIN; if (klo > MS) klo = MS;

    if (excl < khi && khi <= excl + sum) {
        unsigned c = excl;
        #pragma unroll
        for (int i = 0; i < 8; i++) { if (c + h[i] >= khi) { g_bhi[batch] = (unsigned)(top - i); break; } c += h[i]; }
    }
    if (excl < klo && klo <= excl + sum) {
        unsigned c = excl;
        #pragma unroll
        for (int i = 0; i < 8; i++) { if (c + h[i] >= klo) { g_blo[batch] = (unsigned)(top - i); break; } c += h[i]; }
    }
}

// -------- kernel 3: write output, exact above-count, stage window cands ----
__global__ void __launch_bounds__(256) write_kernel(
        const float* __restrict__ x,
        const float* __restrict__ duty,
        const int* __restrict__ kp,
        float* __restrict__ out) {
    __shared__ float              s_fac[NC];
    __shared__ unsigned long long s_buf[STAGE];
    __shared__ unsigned           s_cnt, s_w, s_base;
    int tid = threadIdx.x;
    if (tid < NC) s_fac[tid] = boost_factor(*kp, duty[tid]);
    if (tid == 0) { s_cnt = 0; s_w = 0; }
    __syncthreads();

    int batch = blockIdx.x / CPB_C;
    int slice = blockIdx.x % CPB_C;
    unsigned bhi = g_bhi[batch];
    unsigned blo = g_blo[batch];
    unsigned wspan = bhi - blo;
    unsigned base19 = blo << 19;
    unsigned* h2 = &g_hist2[batch * NBINS];
    const float4* x4 = (const float4*)x + (size_t)batch * NPB4;
    float4*       o4 = (float4*)out     + (size_t)batch * NPB4;
    const int PER = NPB4 / CPB_C;              // 3136
    unsigned wc = 0;

    #pragma unroll 4
    for (int i = tid; i < PER; i += 256) {
        int q = slice * PER + i;
        float f = s_fac[q / HW4];
        float4 v = x4[q];
        unsigned k0 = okey(v.x * f), k1 = okey(v.y * f);
        unsigned k2 = okey(v.z * f), k3 = okey(v.w * f);
        unsigned b0 = k0 >> 19, b1 = k1 >> 19, b2 = k2 >> 19, b3 = k3 >> 19;
        float4 o;
        o.x = (b0 > bhi) ? v.x : 0.0f;
        o.y = (b1 > bhi) ? v.y : 0.0f;
        o.z = (b2 > bhi) ? v.z : 0.0f;
        o.w = (b3 > bhi) ? v.w : 0.0f;
        o4[q] = o;
        wc += (b0 > bhi) + (b1 > bhi) + (b2 > bhi) + (b3 > bhi);
        unsigned e = (unsigned)q * 4u;
        // rare path: ~3-4% of elements land inside the window
        if (b0 - blo <= wspan) {
            atomicAdd(&h2[min((k0 - base19) >> 10, (unsigned)(NBINS - 1))], 1u);
            unsigned p = atomicAdd(&s_cnt, 1u);
            unsigned long long cv = ((unsigned long long)k0 << 32) | (e + 0u);
            if (p < STAGE) s_buf[p] = cv;
            else { unsigned g = atomicAdd(&g_cand_cnt[batch], 1u);
                   if (g < CAP) g_cand[(size_t)batch * CAP + g] = cv; }
        }
        if (b1 - blo <= wspan) {
            atomicAdd(&h2[min((k1 - base19) >> 10, (unsigned)(NBINS - 1))], 1u);
            unsigned p = atomicAdd(&s_cnt, 1u);
            unsigned long long cv = ((unsigned long long)k1 << 32) | (e + 1u);
            if (p < STAGE) s_buf[p] = cv;
            else { unsigned g = atomicAdd(&g_cand_cnt[batch], 1u);
                   if (g < CAP) g_cand[(size_t)batch * CAP + g] = cv; }
        }
        if (b2 - blo <= wspan) {
            atomicAdd(&h2[min((k2 - base19) >> 10, (unsigned)(NBINS - 1))], 1u);
            unsigned p = atomicAdd(&s_cnt, 1u);
            unsigned long long cv = ((unsigned long long)k2 << 32) | (e + 2u);
            if (p < STAGE) s_buf[p] = cv;
            else { unsigned g = atomicAdd(&g_cand_cnt[batch], 1u);
                   if (g < CAP) g_cand[(size_t)batch * CAP + g] = cv; }
        }
        if (b3 - blo <= wspan) {
            atomicAdd(&h2[min((k3 - base19) >> 10, (unsigned)(NBINS - 1))], 1u);
            unsigned p = atomicAdd(&s_cnt, 1u);
            unsigned long long cv = ((unsigned long long)k3 << 32) | (e + 3u);
            if (p < STAGE) s_buf[p] = cv;
            else { unsigned g = atomicAdd(&g_cand_cnt[batch], 1u);
                   if (g < CAP) g_cand[(size_t)batch * CAP + g] = cv; }
        }
    }
    // exact winners-above-window count: one global atomic per CTA
    #pragma unroll
    for (int o = 16; o; o >>= 1) wc += __shfl_down_sync(0xffffffffu, wc, o);
    if ((tid & 31) == 0 && wc) atomicAdd(&s_w, wc);
    __syncthreads();
    if (tid == 0) {
        if (s_w) atomicAdd(&g_above[batch], s_w);
        s_base = atomicAdd(&g_cand_cnt[batch], min(s_cnt, (unsigned)STAGE));
    }
    __syncthreads();
    unsigned cnt = min(s_cnt, (unsigned)STAGE);
    unsigned cb = s_base;
    for (unsigned j = tid; j < cnt; j += 256) {
        unsigned pos = cb + j;
        if (pos < CAP) g_cand[(size_t)batch * CAP + pos] = s_buf[j];
    }
}

// -------- kernel 4: exact selection (parallel scans) or exact fallback -----
__global__ void __launch_bounds__(1024) final_kernel(
        const float* __restrict__ x,
        const float* __restrict__ duty,
        const int* __restrict__ kp,
        float* __restrict__ out) {
    __shared__ unsigned s_w[32];
    __shared__ float    s_fac[NC];
    __shared__ unsigned s_big[NBINS];     // main: stash[0..4095], L2 hist[4096..5119]
    __shared__ unsigned s_sc[8];
    int batch = blockIdx.x, tid = threadIdx.x;
    unsigned k = (unsigned)(*kp);
    unsigned m = g_cand_cnt[batch];
    unsigned above = g_above[batch];
    unsigned blo = g_blo[batch], bhi = g_bhi[batch];
    unsigned long long* cand = &g_cand[(size_t)batch * CAP];
    const float* xb = x   + (size_t)batch * NPB;
    float*       ob = out + (size_t)batch * NPB;

    bool valid = (above < k) && (k <= above + m) && (m <= (unsigned)CAP) &&
                 (bhi - blo < 16u);
    unsigned r = 0, B1 = 0, g1 = 0, eq = 0;
    const unsigned* h2 = &g_hist2[batch * NBINS];

    if (valid) {
        r = k - above;
        if (r >= m) {                       // everything in the window wins
            for (unsigned j = tid; j < m; j += 1024) {
                unsigned idx = (unsigned)cand[j];
                ob[idx] = xb[idx];
            }
            return;
        }
        // level-1: parallel suffix scan on g_hist2 (rel>>10 bins)
        unsigned h[8], sum = 0;
        int top = NBINS - 1 - tid * 8;
        #pragma unroll
        for (int i = 0; i < 8; i++) { h[i] = h2[top - i]; sum += h[i]; }
        unsigned excl = excl_scan1024(sum, s_w, tid);
        if (excl < r && r <= excl + sum) {
            unsigned c = excl;
            #pragma unroll
            for (int i = 0; i < 8; i++) {
                if (c + h[i] >= r) { s_sc[0] = (unsigned)(top - i); s_sc[1] = c; break; }
                c += h[i];
            }
        }
        __syncthreads();
        B1 = s_sc[0]; g1 = s_sc[1];
        eq = h2[B1];
        if (eq > 4096u) valid = false;      // stash overflow -> fallback
    }

    if (valid) {
        // ---------------- fast exact path ----------------
        unsigned base19 = blo << 19;
        unsigned r1 = r - g1;               // needed among the B1 group
        unsigned* s_stash = s_big;          // 4096 packed (rel10<<19)|idx
        unsigned* s_h2    = s_big + 4096;   // 1024-bin L2 hist
        for (int i = tid; i < 1024; i += 1024) s_h2[i] = 0;
        if (tid == 0) s_sc[2] = 0;
        __syncthreads();
        for (unsigned j = tid; j < m; j += 1024) {
            unsigned long long cv = cand[j];
            unsigned rel = (unsigned)(cv >> 32) - base19;
            unsigned hi = rel >> 10;
            unsigned idx = (unsigned)cv;
            if (hi > B1) ob[idx] = xb[idx];          // certain winner
            else if (hi == B1) {
                unsigned p = atomicAdd(&s_sc[2], 1u);
                s_stash[p] = ((rel & 1023u) << 19) | idx;
                atomicAdd(&s_h2[rel & 1023u], 1u);
            }
        }
        __syncthreads();
        unsigned e = s_sc[2];               // == eq <= 4096
        // level-2: parallel suffix scan, one bin per thread
        {
            int b = 1023 - tid;
            unsigned val = (tid < 1024) ? s_h2[b] : 0;
            unsigned excl = excl_scan1024(val, s_w, tid);
            if (excl < r1 && r1 <= excl + val) { s_sc[3] = (unsigned)b; s_sc[4] = r1 - excl; }
        }
        __syncthreads();
        unsigned tl2 = s_sc[3], r2 = s_sc[4];
        // winners among stash; ties at exact threshold by LOWEST index
        for (unsigned j = tid; j < e; j += 1024) {
            unsigned v = s_stash[j];
            unsigned r10 = v >> 19, idx = v & 0x7FFFFu;
            if (r10 > tl2) ob[idx] = xb[idx];
            else if (r10 == tl2) {
                unsigned rank = 0;
                for (unsigned l = 0; l < e; l++) {
                    unsigned w2 = s_stash[l];
                    rank += ((w2 >> 19) == tl2 && (w2 & 0x7FFFFu) < idx) ? 1u : 0u;
                }
                if (rank < r2) ob[idx] = xb[idx];
            }
        }
        return;
    }

    // ---------------- exact fallback: full recompute for this batch --------
    if (tid < NC) s_fac[tid] = boost_factor((int)k, duty[tid]);
    for (int i = tid; i < NBINS; i += 1024) s_big[i] = 0;
    __syncthreads();
    const float4* x4 = (const float4*)xb;
    for (int q = tid; q < NPB4; q += 1024) {
        float f = s_fac[q / HW4];
        float4 v = x4[q];
        atomicAdd(&s_big[okey(v.x * f) >> 19], 1u);
        atomicAdd(&s_big[okey(v.y * f) >> 19], 1u);
        atomicAdd(&s_big[okey(v.z * f) >> 19], 1u);
        atomicAdd(&s_big[okey(v.w * f) >> 19], 1u);
    }
    __syncthreads();
    {   // parallel scan for exact bstar
        unsigned h[8], sum = 0;
        int top = NBINS - 1 - tid * 8;
        #pragma unroll
        for (int i = 0; i < 8; i++) { h[i] = s_big[top - i]; sum += h[i]; }
        unsigned excl = excl_scan1024(sum, s_w, tid);
        if (excl < k && k <= excl + sum) {
            unsigned c = excl;
            #pragma unroll
            for (int i = 0; i < 8; i++) {
                if (c + h[i] >= k) { s_sc[0] = (unsigned)(top - i); s_sc[1] = c; break; }
                c += h[i];
            }
        }
    }
    __syncthreads();
    unsigned bstar = s_sc[0];
    unsigned rr = k - s_sc[1];
    if (tid == 0) s_sc[2] = 0;
    __syncthreads();
    float4* o4 = (float4*)ob;
    for (int q = tid; q < NPB4; q += 1024) {
        float f = s_fac[q / HW4];
        float4 v = x4[q];
        unsigned k0 = okey(v.x * f), k1 = okey(v.y * f);
        unsigned k2 = okey(v.z * f), k3 = okey(v.w * f);
        unsigned b0 = k0 >> 19, b1 = k1 >> 19, b2 = k2 >> 19, b3 = k3 >> 19;
        float4 o;
        o.x = (b0 > bstar) ? v.x : 0.0f;
        o.y = (b1 > bstar) ? v.y : 0.0f;
        o.z = (b2 > bstar) ? v.z : 0.0f;
        o.w = (b3 > bstar) ? v.w : 0.0f;
        o4[q] = o;
        unsigned e = (unsigned)q * 4u;
        if (b0 == bstar) { unsigned p = atomicAdd(&s_sc[2], 1u);
            if (p < CAP) cand[p] = ((unsigned long long)k0 << 32) | (e + 0u); }
        if (b1 == bstar) { unsigned p = atomicAdd(&s_sc[2], 1u);
            if (p < CAP) cand[p] = ((unsigned long long)k1 << 32) | (e + 1u); }
        if (b2 == bstar) { unsigned p = atomicAdd(&s_sc[2], 1u);
            if (p < CAP) cand[p] = ((unsigned long long)k2 << 32) | (e + 2u); }
        if (b3 == bstar) { unsigned p = atomicAdd(&s_sc[2], 1u);
            if (p < CAP) cand[p] = ((unsigned long long)k3 << 32) | (e + 3u); }
    }
    __syncthreads();
    unsigned m2 = min(s_sc[2], (unsigned)CAP);
    if (rr >= m2) {
        for (unsigned j = tid; j < m2; j += 1024) {
            unsigned idx = (unsigned)cand[j];
            ob[idx] = xb[idx];
        }
        return;
    }
    unsigned fb19 = bstar << 19;
    // L1: 512 bins on rel>>10
    for (int i = tid; i < 512; i += 1024) s_big[i] = 0;
    __syncthreads();
    for (unsigned j = tid; j < m2; j += 1024) {
        unsigned rel = (unsigned)(cand[j] >> 32) - fb19;
        atomicAdd(&s_big[rel >> 10], 1u);
    }
    __syncthreads();
    if (tid == 0) {
        unsigned cum = 0;
        for (int b = 511;; b--) {
            unsigned h = s_big[b];
            if (cum + h >= rr) { s_sc[3] = (unsigned)b; s_sc[4] = cum; break; }
            cum += h;
        }
    }
    __syncthreads();
    unsigned tl1 = s_sc[3];
    unsigned r1 = rr - s_sc[4];
    unsigned* s_l2 = s_big + 1024;
    for (int i = tid; i < 1024; i += 1024) s_l2[i] = 0;
    __syncthreads();
    for (unsigned j = tid; j < m2; j += 1024) {
        unsigned rel = (unsigned)(cand[j] >> 32) - fb19;
        if ((rel >> 10) == tl1) atomicAdd(&s_l2[rel & 1023u], 1u);
    }
    __syncthreads();
    if (tid == 0) {
        unsigned cum = 0;
        for (int b = 1023;; b--) {
            unsigned h = s_l2[b];
            if (cum + h >= r1) { s_sc[5] = (unsigned)b; s_sc[6] = r1 - cum; break; }
            cum += h;
        }
    }
    __syncthreads();
    unsigned tl = (tl1 << 10) | s_sc[5];
    unsigned r2 = s_sc[6];
    for (unsigned j = tid; j < m2; j += 1024) {
        unsigned long long cv = cand[j];
        unsigned rel = (unsigned)(cv >> 32) - fb19;
        unsigned idx = (unsigned)cv;
        if (rel > tl) ob[idx] = xb[idx];
        else if (rel == tl) {
            unsigned rank = 0;
            for (unsigned l = 0; l < m2; l++) {
                unsigned long long cw = cand[l];
                rank += (((unsigned)(cw >> 32) - fb19) == tl &&
                         (unsigned)cw < idx) ? 1u : 0u;
            }
            if (rank < r2) ob[idx] = xb[idx];
        }
    }
}

extern "C" void kernel_launch(void* const* d_in, const int* in_sizes, int n_in,
                              void* d_out, int out_size) {
    const float* x    = (const float*)d_in[0];
    const float* duty = (const float*)d_in[1];
    const int*   kp   = (const int*)d_in[2];
    float*       out  = (float*)d_out;

    zero_kernel<<<512, 256>>>();
    sample_kernel<<<NB * CPB_S, 256>>>(x, duty, kp);
    window_kernel<<<NB, 1024>>>(kp);
    write_kernel<<<NB * CPB_C, 256>>>(x, duty, kp, out);
    final_kernel<<<NB, 1024>>>(x, duty, kp, out);
}

// round 7
// speedup vs baseline: 2.7662x; 1.1053x over previous
#include <cuda_runtime.h>
#include <math.h>

// Problem constants (KWinners2d: B=64, C=128, H=W=56)
#define NB      64
#define NC      128
#define HW      3136
#define NPB     401408          // per-batch n = C*H*W
#define NPB4    (NPB/4)         // 100352 float4 per batch
#define HW4     784
#define NBINS   8192            // 13-bit coarse histogram
#define CAP     (1<<17)         // candidate buffer per batch
#define CPB_S   8               // CTAs per batch, sample pass
#define CPB_C   32              // CTAs per batch, write pass
#define STAGE   2048            // per-CTA candidate staging entries
#define MS      50176           // sampled values per batch = NPB/8
#define MARGIN  502             // ~7 sigma of sampled-rank noise

// -------- global scratch (static __device__, no allocation) --------
__device__ unsigned int       g_hist [NB * NBINS];   // sampled coarse hist
__device__ unsigned int       g_cand_cnt[NB];
__device__ unsigned int       g_bhi[NB];
__device__ unsigned int       g_blo[NB];
__device__ unsigned int       g_above[NB];
__device__ unsigned long long g_cand[(size_t)NB * CAP];  // (key<<32)|idx

// order-preserving key for f32: larger float -> larger uint
__device__ __forceinline__ unsigned okey(float f) {
    unsigned u = __float_as_uint(f);
    unsigned s = (unsigned)((int)u >> 31);
    return u ^ (s | 0x80000000u);
}

__device__ __forceinline__ float boost_factor(int k, float duty) {
    float td = (float)((double)k / (double)NPB);
    float arg = td - duty;
    return (float)exp((double)arg);   // correctly-rounded f32 result
}

// block-wide exclusive prefix sum, blockDim.x == 1024 exactly
__device__ __forceinline__ unsigned excl_scan1024(unsigned v, unsigned* s_w, int tid) {
    __syncthreads();                              // protect s_w reuse
    int lane = tid & 31, wid = tid >> 5;
    unsigned inc = v;
    #pragma unroll
    for (int o = 1; o < 32; o <<= 1) {
        unsigned n = __shfl_up_sync(0xffffffffu, inc, o);
        if (lane >= o) inc += n;
    }
    if (lane == 31) s_w[wid] = inc;
    __syncthreads();
    if (wid == 0) {
        unsigned w = s_w[lane];
        #pragma unroll
        for (int o = 1; o < 32; o <<= 1) {
            unsigned n = __shfl_up_sync(0xffffffffu, w, o);
            if (lane >= o) w += n;
        }
        s_w[lane] = w;
    }
    __syncthreads();
    unsigned base = wid ? s_w[wid - 1] : 0u;
    return base + inc - v;
}

// -------- kernel 0: zero scratch (re-zeroed every graph replay) --------
__global__ void zero_kernel() {
    int total = NB * NBINS;
    int tid = blockIdx.x * blockDim.x + threadIdx.x;
    for (int i = tid; i < total; i += gridDim.x * blockDim.x) g_hist[i] = 0;
    if (blockIdx.x == 0 && threadIdx.x < NB) {
        g_cand_cnt[threadIdx.x] = 0;
        g_above[threadIdx.x] = 0;
    }
}

// -------- kernel 1: sampled coarse histogram, 8 CTAs/batch --------
__global__ void __launch_bounds__(256) sample_kernel(
        const float* __restrict__ x,
        const float* __restrict__ duty,
        const int* __restrict__ kp) {
    __shared__ unsigned s_hist[NBINS];
    __shared__ float    s_fac[NC];
    int tid = threadIdx.x;
    for (int i = tid; i < NBINS; i += 256) s_hist[i] = 0;
    if (tid < NC) s_fac[tid] = boost_factor(*kp, duty[tid]);
    __syncthreads();

    int batch = blockIdx.x / CPB_S;
    int slice = blockIdx.x % CPB_S;
    const float4* x4 = (const float4*)x + (size_t)batch * NPB4;
    int base = slice * (NPB4 / CPB_S);         // 12544 region per CTA
    // 1568 sampled float4: warp reads 32 contiguous float4 (512B), skips 8x
    for (int j = tid; j < 1568; j += 256) {
        int q = base + ((j >> 5) << 8) + (j & 31);
        float f = s_fac[q / HW4];
        float4 v = x4[q];
        unsigned b0 = okey(v.x * f) >> 19;
        unsigned b1 = okey(v.y * f) >> 19;
        unsigned b2 = okey(v.z * f) >> 19;
        unsigned b3 = okey(v.w * f) >> 19;
        unsigned c0 = 1, c1 = 1, c2 = 1, c3 = 1;
        if (b1 == b0) { c0++; c1 = 0; }
        if (b2 == b0) { c0++; c2 = 0; }
        else if (c1 && b2 == b1) { c1++; c2 = 0; }
        if (b3 == b0) { c0++; c3 = 0; }
        else if (c1 && b3 == b1) { c1++; c3 = 0; }
        else if (c2 && b3 == b2) { c2++; c3 = 0; }
        atomicAdd(&s_hist[b0], c0);
        if (c1) atomicAdd(&s_hist[b1], c1);
        if (c2) atomicAdd(&s_hist[b2], c2);
        if (c3) atomicAdd(&s_hist[b3], c3);
    }
    __syncthreads();
    unsigned* gh = &g_hist[batch * NBINS];
    for (int i = tid; i < NBINS; i += 256)
        if (s_hist[i]) atomicAdd(&gh[i], s_hist[i]);
}

// -------- kernel 2: pick window [b_lo, b_hi] via parallel suffix scan ------
__global__ void __launch_bounds__(1024) window_kernel(const int* __restrict__ kp) {
    __shared__ unsigned s_w[32];
    int batch = blockIdx.x, tid = threadIdx.x;
    const unsigned* gh = &g_hist[batch * NBINS];
    unsigned h[8], sum = 0;
    int top = NBINS - 1 - tid * 8;
    #pragma unroll
    for (int i = 0; i < 8; i++) { h[i] = gh[top - i]; sum += h[i]; }
    unsigned excl = excl_scan1024(sum, s_w, tid);   // counts in bins above chunk

    unsigned k  = (unsigned)(*kp);
    unsigned ks = (unsigned)((unsigned long long)k * MS / NPB);
    unsigned khi = (ks > MARGIN) ? ks - MARGIN : 1u;
    unsigned klo = ks + MARGIN; if (klo > MS) klo = MS;

    if (excl < khi && khi <= excl + sum) {
        unsigned c = excl;
        #pragma unroll
        for (int i = 0; i < 8; i++) { if (c + h[i] >= khi) { g_bhi[batch] = (unsigned)(top - i); break; } c += h[i]; }
    }
    if (excl < klo && klo <= excl + sum) {
        unsigned c = excl;
        #pragma unroll
        for (int i = 0; i < 8; i++) { if (c + h[i] >= klo) { g_blo[batch] = (unsigned)(top - i); break; } c += h[i]; }
    }
}

// -------- kernel 3: write output, exact above-count, stage window cands ----
__global__ void __launch_bounds__(256) write_kernel(
        const float* __restrict__ x,
        const float* __restrict__ duty,
        const int* __restrict__ kp,
        float* __restrict__ out) {
    __shared__ float              s_fac[NC];
    __shared__ unsigned long long s_buf[STAGE];
    __shared__ unsigned           s_cnt, s_w, s_base;
    int tid = threadIdx.x;
    if (tid < NC) s_fac[tid] = boost_factor(*kp, duty[tid]);
    if (tid == 0) { s_cnt = 0; s_w = 0; }
    __syncthreads();

    int batch = blockIdx.x / CPB_C;
    int slice = blockIdx.x % CPB_C;
    unsigned bhi = g_bhi[batch];
    unsigned blo = g_blo[batch];
    unsigned wspan = bhi - blo;
    const float4* x4 = (const float4*)x + (size_t)batch * NPB4;
    float4*       o4 = (float4*)out     + (size_t)batch * NPB4;
    const int PER = NPB4 / CPB_C;              // 3136
    unsigned wc = 0;

    #pragma unroll 4
    for (int i = tid; i < PER; i += 256) {
        int q = slice * PER + i;
        float f = s_fac[q / HW4];
        float4 v = x4[q];
        unsigned k0 = okey(v.x * f), k1 = okey(v.y * f);
        unsigned k2 = okey(v.z * f), k3 = okey(v.w * f);
        unsigned b0 = k0 >> 19, b1 = k1 >> 19, b2 = k2 >> 19, b3 = k3 >> 19;
        float4 o;
        o.x = (b0 > bhi) ? v.x : 0.0f;
        o.y = (b1 > bhi) ? v.y : 0.0f;
        o.z = (b2 > bhi) ? v.z : 0.0f;
        o.w = (b3 > bhi) ? v.w : 0.0f;
        o4[q] = o;
        wc += (b0 > bhi) + (b1 > bhi) + (b2 > bhi) + (b3 > bhi);
        unsigned e = (unsigned)q * 4u;
        // rare path: ~2% of elements land inside the window
        if (b0 - blo <= wspan) {
            unsigned p = atomicAdd(&s_cnt, 1u);
            unsigned long long cv = ((unsigned long long)k0 << 32) | (e + 0u);
            if (p < STAGE) s_buf[p] = cv;
            else { unsigned g = atomicAdd(&g_cand_cnt[batch], 1u);
                   if (g < CAP) g_cand[(size_t)batch * CAP + g] = cv; }
        }
        if (b1 - blo <= wspan) {
            unsigned p = atomicAdd(&s_cnt, 1u);
            unsigned long long cv = ((unsigned long long)k1 << 32) | (e + 1u);
            if (p < STAGE) s_buf[p] = cv;
            else { unsigned g = atomicAdd(&g_cand_cnt[batch], 1u);
                   if (g < CAP) g_cand[(size_t)batch * CAP + g] = cv; }
        }
        if (b2 - blo <= wspan) {
            unsigned p = atomicAdd(&s_cnt, 1u);
            unsigned long long cv = ((unsigned long long)k2 << 32) | (e + 2u);
            if (p < STAGE) s_buf[p] = cv;
            else { unsigned g = atomicAdd(&g_cand_cnt[batch], 1u);
                   if (g < CAP) g_cand[(size_t)batch * CAP + g] = cv; }
        }
        if (b3 - blo <= wspan) {
            unsigned p = atomicAdd(&s_cnt, 1u);
            unsigned long long cv = ((unsigned long long)k3 << 32) | (e + 3u);
            if (p < STAGE) s_buf[p] = cv;
            else { unsigned g = atomicAdd(&g_cand_cnt[batch], 1u);
                   if (g < CAP) g_cand[(size_t)batch * CAP + g] = cv; }
        }
    }
    // exact winners-above-window count: one global atomic per CTA
    #pragma unroll
    for (int o = 16; o; o >>= 1) wc += __shfl_down_sync(0xffffffffu, wc, o);
    if ((tid & 31) == 0 && wc) atomicAdd(&s_w, wc);
    __syncthreads();
    if (tid == 0) {
        if (s_w) atomicAdd(&g_above[batch], s_w);
        s_base = atomicAdd(&g_cand_cnt[batch], min(s_cnt, (unsigned)STAGE));
    }
    __syncthreads();
    unsigned cnt = min(s_cnt, (unsigned)STAGE);
    unsigned cb = s_base;
    for (unsigned j = tid; j < cnt; j += 256) {
        unsigned pos = cb + j;
        if (pos < CAP) g_cand[(size_t)batch * CAP + pos] = s_buf[j];
    }
}

// -------- kernel 4: exact selection (parallel scans) or exact fallback -----
__global__ void __launch_bounds__(1024) final_kernel(
        const float* __restrict__ x,
        const float* __restrict__ duty,
        const int* __restrict__ kp,
        float* __restrict__ out) {
    __shared__ unsigned s_w[32];
    __shared__ float    s_fac[NC];
    __shared__ unsigned s_big[NBINS];     // hist, then stash[0..4095] + L2 hist[4096..5119]
    __shared__ unsigned s_sc[8];
    int batch = blockIdx.x, tid = threadIdx.x;
    unsigned k = (unsigned)(*kp);
    unsigned m = g_cand_cnt[batch];
    unsigned above = g_above[batch];
    unsigned blo = g_blo[batch], bhi = g_bhi[batch];
    unsigned long long* cand = &g_cand[(size_t)batch * CAP];
    const float* xb = x   + (size_t)batch * NPB;
    float*       ob = out + (size_t)batch * NPB;

    bool valid = (above < k) && (k <= above + m) && (m <= (unsigned)CAP) &&
                 (bhi - blo < 16u);
    unsigned r = 0, B1 = 0, g1 = 0, eq = 0;
    unsigned base19 = blo << 19;

    if (valid) {
        r = k - above;
        if (r >= m) {                       // everything in the window wins
            for (unsigned j = tid; j < m; j += 1024) {
                unsigned idx = (unsigned)cand[j];
                ob[idx] = xb[idx];
            }
            return;
        }
        // build rel-key level-1 histogram (rel>>10, 8192 bins) over candidates
        for (int i = tid; i < NBINS; i += 1024) s_big[i] = 0;
        __syncthreads();
        for (unsigned j = tid; j < m; j += 1024) {
            unsigned rel = (unsigned)(cand[j] >> 32) - base19;   // < 2^23
            atomicAdd(&s_big[rel >> 10], 1u);
        }
        __syncthreads();
        // parallel suffix scan for rank r
        unsigned h[8], sum = 0;
        int top = NBINS - 1 - tid * 8;
        #pragma unroll
        for (int i = 0; i < 8; i++) { h[i] = s_big[top - i]; sum += h[i]; }
        unsigned excl = excl_scan1024(sum, s_w, tid);
        if (excl < r && r <= excl + sum) {
            unsigned c = excl;
            #pragma unroll
            for (int i = 0; i < 8; i++) {
                if (c + h[i] >= r) { s_sc[0] = (unsigned)(top - i); s_sc[1] = c; break; }
                c += h[i];
            }
        }
        __syncthreads();
        B1 = s_sc[0]; g1 = s_sc[1];
        eq = s_big[B1];
        if (eq > 4096u) valid = false;      // stash overflow -> fallback
        __syncthreads();
    }

    if (valid) {
        // ---------------- fast exact path ----------------
        unsigned r1 = r - g1;               // needed among the B1 group
        unsigned* s_stash = s_big;          // 4096 packed (rel10<<19)|idx
        unsigned* s_h2    = s_big + 4096;   // 1024-bin L2 hist
        for (int i = tid; i < 1024; i += 1024) s_h2[i] = 0;
        if (tid == 0) s_sc[2] = 0;
        __syncthreads();
        for (unsigned j = tid; j < m; j += 1024) {
            unsigned long long cv = cand[j];
            unsigned rel = (unsigned)(cv >> 32) - base19;
            unsigned hi = rel >> 10;
            unsigned idx = (unsigned)cv;
            if (hi > B1) ob[idx] = xb[idx];          // certain winner
            else if (hi == B1) {
                unsigned p = atomicAdd(&s_sc[2], 1u);
                if (p < 4096u) {
                    s_stash[p] = ((rel & 1023u) << 19) | idx;
                    atomicAdd(&s_h2[rel & 1023u], 1u);
                }
            }
        }
        __syncthreads();
        unsigned e = min(s_sc[2], 4096u);   // == eq <= 4096
        // level-2: parallel suffix scan, one bin per thread
        {
            int b = 1023 - tid;
            unsigned val = (tid < 1024) ? s_h2[b] : 0;
            unsigned excl = excl_scan1024(val, s_w, tid);
            if (excl < r1 && r1 <= excl + val) { s_sc[3] = (unsigned)b; s_sc[4] = r1 - excl; }
        }
        __syncthreads();
        unsigned tl2 = s_sc[3], r2 = s_sc[4];
        // winners among stash; ties at exact threshold by LOWEST index
        for (unsigned j = tid; j < e; j += 1024) {
            unsigned v = s_stash[j];
            unsigned r10 = v >> 19, idx = v & 0x7FFFFu;
            if (r10 > tl2) ob[idx] = xb[idx];
            else if (r10 == tl2) {
                unsigned rank = 0;
                for (unsigned l = 0; l < e; l++) {
                    unsigned w2 = s_stash[l];
                    rank += ((w2 >> 19) == tl2 && (w2 & 0x7FFFFu) < idx) ? 1u : 0u;
                }
                if (rank < r2) ob[idx] = xb[idx];
            }
        }
        return;
    }

    // ---------------- exact fallback: full recompute for this batch --------
    if (tid < NC) s_fac[tid] = boost_factor((int)k, duty[tid]);
    for (int i = tid; i < NBINS; i += 1024) s_big[i] = 0;
    __syncthreads();
    const float4* x4 = (const float4*)xb;
    for (int q = tid; q < NPB4; q += 1024) {
        float f = s_fac[q / HW4];
        float4 v = x4[q];
        atomicAdd(&s_big[okey(v.x * f) >> 19], 1u);
        atomicAdd(&s_big[okey(v.y * f) >> 19], 1u);
        atomicAdd(&s_big[okey(v.z * f) >> 19], 1u);
        atomicAdd(&s_big[okey(v.w * f) >> 19], 1u);
    }
    __syncthreads();
    {   // parallel scan for exact bstar
        unsigned h[8], sum = 0;
        int top = NBINS - 1 - tid * 8;
        #pragma unroll
        for (int i = 0; i < 8; i++) { h[i] = s_big[top - i]; sum += h[i]; }
        unsigned excl = excl_scan1024(sum, s_w, tid);
        if (excl < k && k <= excl + sum) {
            unsigned c = excl;
            #pragma unroll
            for (int i = 0; i < 8; i++) {
                if (c + h[i] >= k) { s_sc[0] = (unsigned)(top - i); s_sc[1] = c; break; }
                c += h[i];
            }
        }
    }
    __syncthreads();
    unsigned bstar = s_sc[0];
    unsigned rr = k - s_sc[1];
    if (tid == 0) s_sc[2] = 0;
    __syncthreads();
    float4* o4 = (float4*)ob;
    for (int q = tid; q < NPB4; q += 1024) {
        float f = s_fac[q / HW4];
        float4 v = x4[q];
        unsigned k0 = okey(v.x * f), k1 = okey(v.y * f);
        unsigned k2 = okey(v.z * f), k3 = okey(v.w * f);
        unsigned b0 = k0 >> 19, b1 = k1 >> 19, b2 = k2 >> 19, b3 = k3 >> 19;
        float4 o;
        o.x = (b0 > bstar) ? v.x : 0.0f;
        o.y = (b1 > bstar) ? v.y : 0.0f;
        o.z = (b2 > bstar) ? v.z : 0.0f;
        o.w = (b3 > bstar) ? v.w : 0.0f;
        o4[q] = o;
        unsigned e = (unsigned)q * 4u;
        if (b0 == bstar) { unsigned p = atomicAdd(&s_sc[2], 1u);
            if (p < CAP) cand[p] = ((unsigned long long)k0 << 32) | (e + 0u); }
        if (b1 == bstar) { unsigned p = atomicAdd(&s_sc[2], 1u);
            if (p < CAP) cand[p] = ((unsigned long long)k1 << 32) | (e + 1u); }
        if (b2 == bstar) { unsigned p = atomicAdd(&s_sc[2], 1u);
            if (p < CAP) cand[p] = ((unsigned long long)k2 << 32) | (e + 2u); }
        if (b3 == bstar) { unsigned p = atomicAdd(&s_sc[2], 1u);
            if (p < CAP) cand[p] = ((unsigned long long)k3 << 32) | (e + 3u); }
    }
    __syncthreads();
    unsigned m2 = min(s_sc[2], (unsigned)CAP);
    if (rr >= m2) {
        for (unsigned j = tid; j < m2; j += 1024) {
            unsigned idx = (unsigned)cand[j];
            ob[idx] = xb[idx];
        }
        return;
    }
    unsigned fb19 = bstar << 19;
    // L1: 512 bins on rel>>10
    for (int i = tid; i < 512; i += 1024) s_big[i] = 0;
    __syncthreads();
    for (unsigned j = tid; j < m2; j += 1024) {
        unsigned rel = (unsigned)(cand[j] >> 32) - fb19;
        atomicAdd(&s_big[rel >> 10], 1u);
    }
    __syncthreads();
    if (tid == 0) {
        unsigned cum = 0;
        for (int b = 511;; b--) {
            unsigned h = s_big[b];
            if (cum + h >= rr) { s_sc[3] = (unsigned)b; s_sc[4] = cum; break; }
            cum += h;
        }
    }
    __syncthreads();
    unsigned tl1 = s_sc[3];
    unsigned r1 = rr - s_sc[4];
    unsigned* s_l2 = s_big + 1024;
    for (int i = tid; i < 1024; i += 1024) s_l2[i] = 0;
    __syncthreads();
    for (unsigned j = tid; j < m2; j += 1024) {
        unsigned rel = (unsigned)(cand[j] >> 32) - fb19;
        if ((rel >> 10) == tl1) atomicAdd(&s_l2[rel & 1023u], 1u);
    }
    __syncthreads();
    if (tid == 0) {
        unsigned cum = 0;
        for (int b = 1023;; b--) {
            unsigned h = s_l2[b];
            if (cum + h >= r1) { s_sc[5] = (unsigned)b; s_sc[6] = r1 - cum; break; }
            cum += h;
        }
    }
    __syncthreads();
    unsigned tl = (tl1 << 10) | s_sc[5];
    unsigned r2 = s_sc[6];
    for (unsigned j = tid; j < m2; j += 1024) {
        unsigned long long cv = cand[j];
        unsigned rel = (unsigned)(cv >> 32) - fb19;
        unsigned idx = (unsigned)cv;
        if (rel > tl) ob[idx] = xb[idx];
        else if (rel == tl) {
            unsigned rank = 0;
            for (unsigned l = 0; l < m2; l++) {
                unsigned long long cw = cand[l];
                rank += (((unsigned)(cw >> 32) - fb19) == tl &&
                         (unsigned)cw < idx) ? 1u : 0u;
            }
            if (rank < r2) ob[idx] = xb[idx];
        }
    }
}

extern "C" void kernel_launch(void* const* d_in, const int* in_sizes, int n_in,
                              void* d_out, int out_size) {
    const float* x    = (const float*)d_in[0];
    const float* duty = (const float*)d_in[1];
    const int*   kp   = (const int*)d_in[2];
    float*       out  = (float*)d_out;

    zero_kernel<<<512, 256>>>();
    sample_kernel<<<NB * CPB_S, 256>>>(x, duty, kp);
    window_kernel<<<NB, 1024>>>(kp);
    write_kernel<<<NB * CPB_C, 256>>>(x, duty, kp, out);
    final_kernel<<<NB, 1024>>>(x, duty, kp, out);
}